// round 15
// baseline (speedup 1.0000x reference)
#include <cuda_runtime.h>
#include <cuda_fp16.h>

// ---------------------------------------------------------------------------
// PyramidAttention (UrbanODE core), B=32, C=64, H=W=32, 5 scales, N=3278.
//
// R15: logits computed DIRECTLY as a K=288 patch-GEMM (softmax was proven
// instruction-bound on its 9-tap stencil, not memory-bound):
//   Ap[p][(d,c)] = match[p+d][c]  (0 if query-invalid)   19 MB fp16
//   Bp[n][(d,c)] = refm [n+d][c]  (0 if pyramid-invalid) 60 MB fp16
//   logit[p][n]  = invn[n] * (Ap @ Bp^T)   (HMMA, fp32, coalesced rows)
//   softmax      = stencil-free row pass -> e (fp16, padded) + inv[p]
//   T[p,m]       = sum_d inv[p+d] * e[p+d][m+d]   (unchanged)
//   out[c,p]     = x + 0.25 * base @ T            (fp16 HMMA, unchanged)
// ---------------------------------------------------------------------------

namespace {
constexpr int kB   = 32;
constexpr int kC   = 64;
constexpr int kC2  = 32;
constexpr int kHW  = 1024;
constexpr int kN   = 3278;   // 1024+784+625+484+361
constexpr int kNS  = 3280;   // logit row stride (fp32)
constexpr int kNSP = 3808;   // padded-layout row stride (e)
constexpr int kKP  = 288;    // patch K = 9*32
}

// scratch (device globals zero-initialized; guard cells / zero rows never written)
__device__ __half   g_match16[(size_t)kB * kHW * kC2]; // [p][c]
__device__ __half   g_refm16 [(size_t)kB * kN  * kC2]; // [n][c]
__device__ __half   g_base16 [(size_t)kB * kC  * kN];  // [c][n]
__device__ __half   g_Ap     [(size_t)kB * kHW * kKP]; // [p][288]
__device__ __half   g_Bp     [(size_t)kB * kN  * kKP]; // [n][288]
__device__ float    g_sqp    [(size_t)kB * kNSP];
__device__ float    g_invn   [(size_t)kB * kN];
__device__ float    g_inv    [(size_t)kB * kHW];
__device__ unsigned g_mapn   [kN];                     // np | (ws<<16)
__device__ __half   g_zeroH  [kNSP + 64];              // never written
__device__ float    g_logit  [(size_t)kB * kHW * kNS];
__device__ __half   g_e      [(size_t)kB * kHW * kNSP];
__device__ __half   g_T      [(size_t)kB * kHW * kNS];

// pyramid pixel -> (level-local y, x, level width)
__device__ __forceinline__ void n_geom(int n, int& ny, int& nx, int& wl)
{
    if (n < 1024)      { int loc = n;        ny = loc >> 5;  nx = loc & 31;     wl = 32; }
    else if (n < 1808) { int loc = n - 1024; ny = loc / 28;  nx = loc - ny*28;  wl = 28; }
    else if (n < 2433) { int loc = n - 1808; ny = loc / 25;  nx = loc - ny*25;  wl = 25; }
    else if (n < 2917) { int loc = n - 2433; ny = loc / 22;  nx = loc - ny*22;  wl = 22; }
    else               { int loc = n - 2917; ny = loc / 19;  nx = loc - ny*19;  wl = 19; }
}

// valid n -> padded index np and padded width ws
__device__ __forceinline__ void n_pad(int n, int& np, int& ws)
{
    int ny, nx, wl;
    n_geom(n, ny, nx, wl);
    int pb;
    if (n < 1024)      pb = 0;
    else if (n < 1808) pb = 1156;
    else if (n < 2433) pb = 2056;
    else if (n < 2917) pb = 2785;
    else               pb = 3361;
    ws = wl + 2;
    np = pb + (ny + 1) * ws + (nx + 1);
}

// ---------------------------------------------------------------------------
// Pyramid projections: refm16 [n][c] + sq + base16 [c][n] + mapn.
// ---------------------------------------------------------------------------
__global__ __launch_bounds__(256) void k_conv_pyr(
    const float* __restrict__ x,
    const float* __restrict__ w_match, const float* __restrict__ b_match,
    const float* __restrict__ a_match,
    const float* __restrict__ w_asm,   const float* __restrict__ b_asm,
    const float* __restrict__ a_asm)
{
    __shared__ float ws[kC2 * kC + kC * kC];
    int b = blockIdx.y;
    int tid = threadIdx.x;
    for (int i = tid; i < kC2 * kC; i += 256) ws[i] = w_match[i];
    for (int i = tid; i < kC * kC; i += 256)  ws[kC2 * kC + i] = w_asm[i];
    __syncthreads();
    int n = blockIdx.x * 256 + tid;
    if (n >= kN) return;

    int ny, nx, wl;
    n_geom(n, ny, nx, wl);
    int sy = (ny * 32) / wl;
    int sx = (nx * 32) / wl;
    const float* xb = x + ((size_t)b * kC) * kHW + sy * 32 + sx;

    float accM[kC2], accA[kC];
#pragma unroll
    for (int co = 0; co < kC2; co++) accM[co] = b_match[co];
#pragma unroll
    for (int co = 0; co < kC; co++)  accA[co] = b_asm[co];
#pragma unroll 2
    for (int c = 0; c < kC; c++) {
        float xv = xb[(size_t)c * kHW];
#pragma unroll
        for (int co = 0; co < kC2; co++) accM[co] = fmaf(ws[co * kC + c], xv, accM[co]);
#pragma unroll
        for (int co = 0; co < kC; co++)  accA[co] = fmaf(ws[kC2 * kC + co * kC + c], xv, accA[co]);
    }
    float alM = a_match[0], alA = a_asm[0];
    __half* obM = g_refm16 + ((size_t)b * kN + n) * kC2;
    float sq = 0.f;
#pragma unroll
    for (int co = 0; co < kC2; co++) {
        float v = accM[co];
        v = v >= 0.f ? v : alM * v;
        obM[co] = __float2half(v);
        sq = fmaf(v, v, sq);
    }
    __half* obA = g_base16 + (size_t)b * kC * kN + n;
#pragma unroll
    for (int co = 0; co < kC; co++) {
        float v = accA[co];
        v = v >= 0.f ? v : alA * v;
        obA[(size_t)co * kN] = __float2half(v);
    }
    int np, wss;
    n_pad(n, np, wss);
    g_sqp[(size_t)b * kNSP + np] = sq;
    if (b == 0) g_mapn[n] = (unsigned)np | ((unsigned)wss << 16);
}

// ---------------------------------------------------------------------------
// Main projection: match16 [p][c] fp16. Tail: invnorm.
// ---------------------------------------------------------------------------
__global__ __launch_bounds__(256) void k_conv_main(
    const float* __restrict__ x, const float* __restrict__ w,
    const float* __restrict__ bias, const float* __restrict__ a)
{
    __shared__ float ws[kC2 * kC];
    int b = blockIdx.y;
    int tid = threadIdx.x;
    for (int i = tid; i < kC2 * kC; i += 256) ws[i] = w[i];
    __syncthreads();
    int p = blockIdx.x * 256 + tid;
    const float* xb = x + ((size_t)b * kC) * kHW + p;
    float acc[kC2];
#pragma unroll
    for (int co = 0; co < kC2; co++) acc[co] = bias[co];
#pragma unroll 2
    for (int c = 0; c < kC; c++) {
        float xv = xb[(size_t)c * kHW];
#pragma unroll
        for (int co = 0; co < kC2; co++) acc[co] = fmaf(ws[co * kC + c], xv, acc[co]);
    }
    float al = a[0];
    __half* ob = g_match16 + ((size_t)b * kHW + p) * kC2;
#pragma unroll
    for (int co = 0; co < kC2; co++) {
        float v = acc[co];
        ob[co] = __float2half(v >= 0.f ? v : al * v);
    }

    // ---- invnorm tail: grid-stride over all (b,n) ----
    int nthreads = gridDim.x * gridDim.y * 256;
    int gid0 = (b * gridDim.x + blockIdx.x) * 256 + tid;
    for (int t = gid0; t < kB * kN; t += nthreads) {
        int n = t % kN, bb = t / kN;
        unsigned u = g_mapn[n];
        int np = (int)(u & 0xFFFFu), wss = (int)(u >> 16);
        const float* sp = g_sqp + (size_t)bb * kNSP;
        int cm = np - wss, cp = np + wss;
        float s = sp[cm-1] + sp[cm] + sp[cm+1]
                + sp[np-1] + sp[np] + sp[np+1]
                + sp[cp-1] + sp[cp] + sp[cp+1];
        g_invn[t] = 10.f / fmaxf(sqrtf(s), 1e-4f);
    }
}

// ---------------------------------------------------------------------------
// Patch-operand builder. One uint (2 halves) per thread.
// blockIdx.x < 576: Ap (query patches); else Bp (pyramid patches).
// ---------------------------------------------------------------------------
__global__ __launch_bounds__(256) void k_patch()
{
    int b = blockIdx.y;
    int tid = threadIdx.x;
    if (blockIdx.x < 576) {
        int idx = blockIdx.x * 256 + tid;                 // < 1024*144
        int p  = idx / 144, ku = idx - p * 144;
        int d  = ku >> 4, c2 = ku & 15;
        int dy = d / 3 - 1, dx = d - (d / 3) * 3 - 1;
        int py = p >> 5, px = p & 31;
        int qy = py + dy, qx = px + dx;
        unsigned v = 0;
        if ((unsigned)qy < 32u && (unsigned)qx < 32u)
            v = *(const unsigned*)(g_match16 + ((size_t)b * kHW + qy * 32 + qx) * kC2 + c2 * 2);
        ((unsigned*)g_Ap)[((size_t)b * kHW + p) * 144 + ku] = v;
    } else {
        int idx = (blockIdx.x - 576) * 256 + tid;
        if (idx >= kN * 144) return;
        int n  = idx / 144, ku = idx - n * 144;
        int d  = ku >> 4, c2 = ku & 15;
        int dy = d / 3 - 1, dx = d - (d / 3) * 3 - 1;
        int ny, nx, wl;
        n_geom(n, ny, nx, wl);
        int my = ny + dy, mx = nx + dx;
        unsigned v = 0;
        if ((unsigned)my < (unsigned)wl && (unsigned)mx < (unsigned)wl)
            v = *(const unsigned*)(g_refm16 + ((size_t)b * kN + (n + dy * wl + dx)) * kC2 + c2 * 2);
        ((unsigned*)g_Bp)[((size_t)b * kN + n) * 144 + ku] = v;
    }
}

// ---------------------------------------------------------------------------
// Patch-GEMM: logit[b][p][n] = invn[n] * sum_{k<288} Ap[p][k] * Bp[n][k]
// 128p x 128n block, 9 chunks of BK=32. 8 warps = 4(p) x 2(n), warp 32x64.
// Coalesced fp32 row stores (no scatter).
// ---------------------------------------------------------------------------
__global__ __launch_bounds__(256) void k_gemm1p()
{
    constexpr int SA = 40;
    __shared__ __half As[128 * SA];
    __shared__ __half Bs[128 * SA];
    __shared__ float inv_s[128];
    int b  = blockIdx.z;
    int p0 = blockIdx.y * 128;
    int n0 = blockIdx.x * 128;
    const __half* Ab = g_Ap + (size_t)b * kHW * kKP;
    const __half* Bb = g_Bp + (size_t)b * kN  * kKP;
    int tid  = threadIdx.x;
    int lane = tid & 31, warp = tid >> 5;
    int wm = (warp & 3) * 32;
    int wn = (warp >> 2) * 64;
    int gid = lane >> 2, tig = lane & 3;

    if (tid < 128) {
        int n = n0 + tid;
        inv_s[tid] = (n < kN) ? g_invn[(size_t)b * kN + n] : 0.f;
    }

    float acc[2][8][4] = {};
    for (int kc = 0; kc < 9; kc++) {
        __syncthreads();
#pragma unroll
        for (int j = 0; j < 8; j++) {
            int i = tid + j * 256;
            int row = i >> 4, ku = i & 15;
            *(unsigned*)(&As[row * SA + ku * 2]) =
                *(const unsigned*)(Ab + (size_t)(p0 + row) * kKP + kc * 32 + ku * 2);
            int n = n0 + row;
            unsigned v = 0;
            if (n < kN)
                v = *(const unsigned*)(Bb + (size_t)n * kKP + kc * 32 + ku * 2);
            *(unsigned*)(&Bs[row * SA + ku * 2]) = v;
        }
        __syncthreads();
#pragma unroll
        for (int ks = 0; ks < 2; ks++) {
            int kb = ks * 16;
            unsigned a[2][4], bf[8][2];
#pragma unroll
            for (int mt = 0; mt < 2; mt++) {
                const __half* ap = &As[(wm + mt * 16 + gid) * SA + kb + tig * 2];
                a[mt][0] = *(const unsigned*)(ap);
                a[mt][1] = *(const unsigned*)(ap + 8 * SA);
                a[mt][2] = *(const unsigned*)(ap + 8);
                a[mt][3] = *(const unsigned*)(ap + 8 * SA + 8);
            }
#pragma unroll
            for (int nt = 0; nt < 8; nt++) {
                const __half* bp = &Bs[(wn + nt * 8 + gid) * SA + kb + tig * 2];
                bf[nt][0] = *(const unsigned*)(bp);
                bf[nt][1] = *(const unsigned*)(bp + 8);
            }
#pragma unroll
            for (int mt = 0; mt < 2; mt++)
#pragma unroll
                for (int nt = 0; nt < 8; nt++) {
                    asm volatile(
                        "mma.sync.aligned.m16n8k16.row.col.f32.f16.f16.f32 "
                        "{%0,%1,%2,%3}, {%4,%5,%6,%7}, {%8,%9}, {%0,%1,%2,%3};"
                        : "+f"(acc[mt][nt][0]), "+f"(acc[mt][nt][1]),
                          "+f"(acc[mt][nt][2]), "+f"(acc[mt][nt][3])
                        : "r"(a[mt][0]), "r"(a[mt][1]), "r"(a[mt][2]), "r"(a[mt][3]),
                          "r"(bf[nt][0]), "r"(bf[nt][1]));
                }
        }
    }

    // epilogue: invn scale + coalesced float2 stores (pairs always same validity)
    float* Lb = g_logit + (size_t)b * kHW * kNS;
#pragma unroll
    for (int mt = 0; mt < 2; mt++) {
        int r0 = p0 + wm + mt * 16 + gid;
#pragma unroll
        for (int nt = 0; nt < 8; nt++) {
            int cl = wn + nt * 8 + tig * 2;
            int n  = n0 + cl;
            if (n < kN) {
                float iv0 = inv_s[cl], iv1 = inv_s[cl + 1];
                *(float2*)(&Lb[(size_t)r0 * kNS + n]) =
                    make_float2(acc[mt][nt][0] * iv0, acc[mt][nt][1] * iv1);
                *(float2*)(&Lb[(size_t)(r0 + 8) * kNS + n]) =
                    make_float2(acc[mt][nt][2] * iv0, acc[mt][nt][3] * iv1);
            }
        }
    }
}

// ---------------------------------------------------------------------------
// Stencil-free softmax: row max, e=exp(logit-max) -> g_e (padded), inv[p].
// ---------------------------------------------------------------------------
__global__ __launch_bounds__(256) void k_softmax()
{
    __shared__ float row[kNS];
    __shared__ float red[8];
    int p = blockIdx.x, b = blockIdx.y;
    int tid = threadIdx.x;
    int lane = tid & 31, wid = tid >> 5;
    const float* L = g_logit + ((size_t)b * kHW + p) * kNS;

    float mx = -3.4e38f;
    for (int n = tid; n < kN; n += 256) {
        float v = L[n];
        row[n] = v;
        mx = fmaxf(mx, v);
    }
#pragma unroll
    for (int o = 16; o; o >>= 1) mx = fmaxf(mx, __shfl_xor_sync(0xffffffffu, mx, o));
    if (lane == 0) red[wid] = mx;
    __syncthreads();
    mx = red[0];
#pragma unroll
    for (int i = 1; i < 8; i++) mx = fmaxf(mx, red[i]);
    __syncthreads();

    float sum = 0.f;
    __half* eo = g_e + ((size_t)b * kHW + p) * kNSP;
    for (int n = tid; n < kN; n += 256) {
        float e = __expf(row[n] - mx);
        sum += e;
        eo[g_mapn[n] & 0xFFFFu] = __float2half(e);
    }
#pragma unroll
    for (int o = 16; o; o >>= 1) sum += __shfl_xor_sync(0xffffffffu, sum, o);
    if (lane == 0) red[wid] = sum;
    __syncthreads();
    if (tid == 0) {
        float s = red[0];
#pragma unroll
        for (int i = 1; i < 8; i++) s += red[i];
        g_inv[(size_t)b * kHW + p] = 1.f / s;
    }
}

// block-uniform p-side validity + q-row indices
__device__ __forceinline__ unsigned p_taps(int p, int* qrow)
{
    int py = p >> 5, px = p & 31;
    unsigned pm = 0;
    int i = 0;
#pragma unroll
    for (int dy = -1; dy <= 1; dy++)
#pragma unroll
        for (int dx = -1; dx <= 1; dx++, i++) {
            int qy = py + dy, qx = px + dx;
            qrow[i] = qy * 32 + qx;
            if ((unsigned)qy < 32u && (unsigned)qx < 32u) pm |= 1u << i;
        }
    return pm;
}

// ---------------------------------------------------------------------------
// T[b][p][n] = sum_d inv[p+d] * e[b][p+d][np+d]  (block per (p,b); hoisted)
// ---------------------------------------------------------------------------
__global__ __launch_bounds__(256) void k_stencilT()
{
    int p = blockIdx.x, b = blockIdx.y;
    int tid = threadIdx.x;

    int qrow[9];
    unsigned pm = p_taps(p, qrow);
    const __half* E = g_e + (size_t)b * kHW * kNSP;
    const __half* Eq[9];
    float iv[9];
#pragma unroll
    for (int i = 0; i < 9; i++) {
        bool v = (pm >> i) & 1u;
        Eq[i] = v ? (E + (size_t)qrow[i] * kNSP) : g_zeroH;
        iv[i] = v ? g_inv[(size_t)b * kHW + qrow[i]] : 0.f;
    }
    __half* To = g_T + ((size_t)b * kHW + p) * kNS;

#pragma unroll 2
    for (int n = tid; n < kN; n += 256) {
        unsigned u = g_mapn[n];
        int np = (int)(u & 0xFFFFu), wss = (int)(u >> 16);
        int cm = np - wss, cp = np + wss;
        float s;
        s = iv[0] * __half2float(Eq[0][cm - 1]);
        s = fmaf(iv[1], __half2float(Eq[1][cm]),     s);
        s = fmaf(iv[2], __half2float(Eq[2][cm + 1]), s);
        s = fmaf(iv[3], __half2float(Eq[3][np - 1]), s);
        s = fmaf(iv[4], __half2float(Eq[4][np]),     s);
        s = fmaf(iv[5], __half2float(Eq[5][np + 1]), s);
        s = fmaf(iv[6], __half2float(Eq[6][cp - 1]), s);
        s = fmaf(iv[7], __half2float(Eq[7][cp]),     s);
        s = fmaf(iv[8], __half2float(Eq[8][cp + 1]), s);
        To[n] = __float2half(s);
    }
}

// ---------------------------------------------------------------------------
// GEMM2 on tensor cores: out[b][c][p] = x[b][c][p] + 0.25*sum_m base*T
// 64c x 128p, BK=64; 8 warps 2(c)x4(p); m16n8k16 HMMA fp32 acc (R7-proven).
// ---------------------------------------------------------------------------
__global__ __launch_bounds__(256) void k_gemm2(
    const float* __restrict__ x, float* __restrict__ out)
{
    constexpr int BK = 64;
    constexpr int SA = 72;
    __shared__ __half As[64 * SA];
    __shared__ __half Bs[128 * SA];
    int b  = blockIdx.y;
    int p0 = blockIdx.x * 128;
    const __half* Ab = g_base16 + (size_t)b * kC * kN;
    const __half* Tb = g_T      + (size_t)b * kHW * kNS;
    int tid  = threadIdx.x;
    int lane = tid & 31, warp = tid >> 5;
    int wc = (warp & 1) * 32;
    int wp = (warp >> 1) * 32;
    int gid = lane >> 2, tig = lane & 3;
    float acc[2][4][4] = {};

    for (int k0 = 0; k0 < kN; k0 += BK) {
#pragma unroll
        for (int j = 0; j < 8; j++) {
            int idx = tid + j * 256;
            int c = idx >> 5, kk = (idx & 31) * 2;
            int k = k0 + kk;
            unsigned v = 0;
            if (k < kN) v = *(const unsigned*)(Ab + (size_t)c * kN + k);
            *(unsigned*)(&As[c * SA + kk]) = v;
        }
#pragma unroll
        for (int j = 0; j < 16; j++) {
            int idx = tid + j * 256;
            int pp = idx >> 5, kk = (idx & 31) * 2;
            int k = k0 + kk;
            unsigned v = 0;
            if (k < kN) v = *(const unsigned*)(Tb + (size_t)(p0 + pp) * kNS + k);
            *(unsigned*)(&Bs[pp * SA + kk]) = v;
        }
        __syncthreads();
#pragma unroll
        for (int ks = 0; ks < 4; ks++) {
            int kb = ks * 16;
            unsigned a[2][4], bf[4][2];
#pragma unroll
            for (int mt = 0; mt < 2; mt++) {
                const __half* ap = &As[(wc + mt * 16 + gid) * SA + kb + tig * 2];
                a[mt][0] = *(const unsigned*)(ap);
                a[mt][1] = *(const unsigned*)(ap + 8 * SA);
                a[mt][2] = *(const unsigned*)(ap + 8);
                a[mt][3] = *(const unsigned*)(ap + 8 * SA + 8);
            }
#pragma unroll
            for (int nt = 0; nt < 4; nt++) {
                const __half* bp = &Bs[(wp + nt * 8 + gid) * SA + kb + tig * 2];
                bf[nt][0] = *(const unsigned*)(bp);
                bf[nt][1] = *(const unsigned*)(bp + 8);
            }
#pragma unroll
            for (int mt = 0; mt < 2; mt++)
#pragma unroll
                for (int nt = 0; nt < 4; nt++) {
                    asm volatile(
                        "mma.sync.aligned.m16n8k16.row.col.f32.f16.f16.f32 "
                        "{%0,%1,%2,%3}, {%4,%5,%6,%7}, {%8,%9}, {%0,%1,%2,%3};"
                        : "+f"(acc[mt][nt][0]), "+f"(acc[mt][nt][1]),
                          "+f"(acc[mt][nt][2]), "+f"(acc[mt][nt][3])
                        : "r"(a[mt][0]), "r"(a[mt][1]), "r"(a[mt][2]), "r"(a[mt][3]),
                          "r"(bf[nt][0]), "r"(bf[nt][1]));
                }
        }
        __syncthreads();
    }

    const float* xb = x   + (size_t)b * kC * kHW;
    float*       ob = out + (size_t)b * kC * kHW;
#pragma unroll
    for (int mt = 0; mt < 2; mt++) {
        int c = wc + mt * 16 + gid;
#pragma unroll
        for (int nt = 0; nt < 4; nt++) {
            int pc = p0 + wp + nt * 8 + tig * 2;
            ob[(size_t)c * kHW + pc]           = fmaf(0.25f, acc[mt][nt][0], xb[(size_t)c * kHW + pc]);
            ob[(size_t)c * kHW + pc + 1]       = fmaf(0.25f, acc[mt][nt][1], xb[(size_t)c * kHW + pc + 1]);
            ob[(size_t)(c + 8) * kHW + pc]     = fmaf(0.25f, acc[mt][nt][2], xb[(size_t)(c + 8) * kHW + pc]);
            ob[(size_t)(c + 8) * kHW + pc + 1] = fmaf(0.25f, acc[mt][nt][3], xb[(size_t)(c + 8) * kHW + pc + 1]);
        }
    }
}

// ---------------------------------------------------------------------------
extern "C" void kernel_launch(void* const* d_in, const int* in_sizes, int n_in,
                              void* d_out, int out_size)
{
    (void)in_sizes; (void)n_in; (void)out_size;
    const float* x       = (const float*)d_in[0];
    const float* w_base  = (const float*)d_in[1];
    const float* b_base  = (const float*)d_in[2];
    const float* a_base  = (const float*)d_in[3];
    const float* w_match = (const float*)d_in[4];
    const float* b_match = (const float*)d_in[5];
    const float* a_match = (const float*)d_in[6];
    const float* w_asm   = (const float*)d_in[7];
    const float* b_asm   = (const float*)d_in[8];
    const float* a_asm   = (const float*)d_in[9];
    float* out = (float*)d_out;

    {
        dim3 g(13, kB);
        k_conv_pyr<<<g, 256>>>(x, w_match, b_match, a_match, w_asm, b_asm, a_asm); // 1
    }
    {
        dim3 g(4, kB);
        k_conv_main<<<g, 256>>>(x, w_base, b_base, a_base);                        // 2 (+invn tail)
    }
    {
        // Ap: 1024*144/256 = 576 blocks; Bp: ceil(3278*144/256) = 1844 blocks
        dim3 g(576 + 1844, kB);
        k_patch<<<g, 256>>>();                                                     // 3
    }
    {
        dim3 g((kN + 127) / 128, kHW / 128, kB);
        k_gemm1p<<<g, 256>>>();                                                    // 4 (profiled)
    }
    {
        dim3 g(kHW, kB);
        k_softmax<<<g, 256>>>();                                                   // 5
        k_stencilT<<<g, 256>>>();                                                  // 6
    }
    {
        dim3 g(kHW / 128, kB);
        k_gemm2<<<g, 256>>>(x, out);                                               // 7
    }
}

// round 16
// speedup vs baseline: 1.0560x; 1.0560x over previous
#include <cuda_runtime.h>
#include <cuda_fp16.h>

// ---------------------------------------------------------------------------
// PyramidAttention (UrbanODE core), B=32, C=64, H=W=32, 5 scales, N=3278.
//
// R16: (a) gemm1p pipelined: A-tile resident + cp.async double-buffered B
//      (R15 had no overlap: 1 block/SM, sync-load-sync-MMA => 378us);
//      smem-staged coalesced epilogue; 64p x 128n tiles (acc 32 regs).
//      (b) softmax exp via ex2.approx.f16x2 (2 exps/MUFU op; 10*log2e folded
//      into invn exactly) — softmax was at its 107M-__expf MUFU floor.
// ---------------------------------------------------------------------------

namespace {
constexpr int kB   = 32;
constexpr int kC   = 64;
constexpr int kC2  = 32;
constexpr int kHW  = 1024;
constexpr int kN   = 3278;   // 1024+784+625+484+361
constexpr int kNS  = 3280;   // logit row stride (fp32)
constexpr int kNSP = 3808;   // padded-layout row stride (e)
constexpr int kKP  = 288;    // patch K = 9*32
constexpr int kG1Smem = 64 * 296 * 2 + 2 * 128 * 40 * 2;  // 58368 B
}

#define CP_ASYNC16(dst_u32, src_ptr) \
    asm volatile("cp.async.ca.shared.global [%0], [%1], 16;" \
                 :: "r"(dst_u32), "l"(src_ptr))
#define CP_COMMIT()  asm volatile("cp.async.commit_group;")
#define CP_WAIT1()   asm volatile("cp.async.wait_group 1;")

// scratch (device globals zero-initialized; guard cells / zero rows never written)
__device__ __half   g_match16[(size_t)kB * kHW * kC2]; // [p][c]
__device__ __half   g_refm16 [(size_t)kB * kN  * kC2]; // [n][c]
__device__ __half   g_base16 [(size_t)kB * kC  * kN];  // [c][n]
__device__ __half   g_Ap     [(size_t)kB * kHW * kKP]; // [p][288]
__device__ __half   g_Bp     [(size_t)kB * kN  * kKP + 128 * kKP]; // +tail pad
__device__ float    g_sqp    [(size_t)kB * kNSP];
__device__ float    g_invn   [(size_t)kB * kN];        // includes 10*log2e
__device__ float    g_inv    [(size_t)kB * kHW];
__device__ unsigned g_mapn   [kN];                     // np | (ws<<16)
__device__ __half   g_zeroH  [kNSP + 64];              // never written
__device__ float    g_logit  [(size_t)kB * kHW * kNS];
__device__ __half   g_e      [(size_t)kB * kHW * kNSP];
__device__ __half   g_T      [(size_t)kB * kHW * kNS];

// pyramid pixel -> (level-local y, x, level width)
__device__ __forceinline__ void n_geom(int n, int& ny, int& nx, int& wl)
{
    if (n < 1024)      { int loc = n;        ny = loc >> 5;  nx = loc & 31;     wl = 32; }
    else if (n < 1808) { int loc = n - 1024; ny = loc / 28;  nx = loc - ny*28;  wl = 28; }
    else if (n < 2433) { int loc = n - 1808; ny = loc / 25;  nx = loc - ny*25;  wl = 25; }
    else if (n < 2917) { int loc = n - 2433; ny = loc / 22;  nx = loc - ny*22;  wl = 22; }
    else               { int loc = n - 2917; ny = loc / 19;  nx = loc - ny*19;  wl = 19; }
}

// valid n -> padded index np and padded width ws
__device__ __forceinline__ void n_pad(int n, int& np, int& ws)
{
    int ny, nx, wl;
    n_geom(n, ny, nx, wl);
    int pb;
    if (n < 1024)      pb = 0;
    else if (n < 1808) pb = 1156;
    else if (n < 2433) pb = 2056;
    else if (n < 2917) pb = 2785;
    else               pb = 3361;
    ws = wl + 2;
    np = pb + (ny + 1) * ws + (nx + 1);
}

// ---------------------------------------------------------------------------
// Pyramid projections: refm16 [n][c] + sq + base16 [c][n] + mapn.
// ---------------------------------------------------------------------------
__global__ __launch_bounds__(256) void k_conv_pyr(
    const float* __restrict__ x,
    const float* __restrict__ w_match, const float* __restrict__ b_match,
    const float* __restrict__ a_match,
    const float* __restrict__ w_asm,   const float* __restrict__ b_asm,
    const float* __restrict__ a_asm)
{
    __shared__ float ws[kC2 * kC + kC * kC];
    int b = blockIdx.y;
    int tid = threadIdx.x;
    for (int i = tid; i < kC2 * kC; i += 256) ws[i] = w_match[i];
    for (int i = tid; i < kC * kC; i += 256)  ws[kC2 * kC + i] = w_asm[i];
    __syncthreads();
    int n = blockIdx.x * 256 + tid;
    if (n >= kN) return;

    int ny, nx, wl;
    n_geom(n, ny, nx, wl);
    int sy = (ny * 32) / wl;
    int sx = (nx * 32) / wl;
    const float* xb = x + ((size_t)b * kC) * kHW + sy * 32 + sx;

    float accM[kC2], accA[kC];
#pragma unroll
    for (int co = 0; co < kC2; co++) accM[co] = b_match[co];
#pragma unroll
    for (int co = 0; co < kC; co++)  accA[co] = b_asm[co];
#pragma unroll 2
    for (int c = 0; c < kC; c++) {
        float xv = xb[(size_t)c * kHW];
#pragma unroll
        for (int co = 0; co < kC2; co++) accM[co] = fmaf(ws[co * kC + c], xv, accM[co]);
#pragma unroll
        for (int co = 0; co < kC; co++)  accA[co] = fmaf(ws[kC2 * kC + co * kC + c], xv, accA[co]);
    }
    float alM = a_match[0], alA = a_asm[0];
    __half* obM = g_refm16 + ((size_t)b * kN + n) * kC2;
    float sq = 0.f;
#pragma unroll
    for (int co = 0; co < kC2; co++) {
        float v = accM[co];
        v = v >= 0.f ? v : alM * v;
        obM[co] = __float2half(v);
        sq = fmaf(v, v, sq);
    }
    __half* obA = g_base16 + (size_t)b * kC * kN + n;
#pragma unroll
    for (int co = 0; co < kC; co++) {
        float v = accA[co];
        v = v >= 0.f ? v : alA * v;
        obA[(size_t)co * kN] = __float2half(v);
    }
    int np, wss;
    n_pad(n, np, wss);
    g_sqp[(size_t)b * kNSP + np] = sq;
    if (b == 0) g_mapn[n] = (unsigned)np | ((unsigned)wss << 16);
}

// ---------------------------------------------------------------------------
// Main projection: match16 [p][c] fp16. Tail: invnorm (x 10*log2e).
// ---------------------------------------------------------------------------
__global__ __launch_bounds__(256) void k_conv_main(
    const float* __restrict__ x, const float* __restrict__ w,
    const float* __restrict__ bias, const float* __restrict__ a)
{
    __shared__ float ws[kC2 * kC];
    int b = blockIdx.y;
    int tid = threadIdx.x;
    for (int i = tid; i < kC2 * kC; i += 256) ws[i] = w[i];
    __syncthreads();
    int p = blockIdx.x * 256 + tid;
    const float* xb = x + ((size_t)b * kC) * kHW + p;
    float acc[kC2];
#pragma unroll
    for (int co = 0; co < kC2; co++) acc[co] = bias[co];
#pragma unroll 2
    for (int c = 0; c < kC; c++) {
        float xv = xb[(size_t)c * kHW];
#pragma unroll
        for (int co = 0; co < kC2; co++) acc[co] = fmaf(ws[co * kC + c], xv, acc[co]);
    }
    float al = a[0];
    __half* ob = g_match16 + ((size_t)b * kHW + p) * kC2;
#pragma unroll
    for (int co = 0; co < kC2; co++) {
        float v = acc[co];
        ob[co] = __float2half(v >= 0.f ? v : al * v);
    }

    // ---- invnorm tail (folds softmax_scale * log2(e) = 14.4269504) ----
    int nthreads = gridDim.x * gridDim.y * 256;
    int gid0 = (b * gridDim.x + blockIdx.x) * 256 + tid;
    for (int t = gid0; t < kB * kN; t += nthreads) {
        int n = t % kN, bb = t / kN;
        unsigned u = g_mapn[n];
        int np = (int)(u & 0xFFFFu), wss = (int)(u >> 16);
        const float* sp = g_sqp + (size_t)bb * kNSP;
        int cm = np - wss, cp = np + wss;
        float s = sp[cm-1] + sp[cm] + sp[cm+1]
                + sp[np-1] + sp[np] + sp[np+1]
                + sp[cp-1] + sp[cp] + sp[cp+1];
        g_invn[t] = 14.4269504f / fmaxf(sqrtf(s), 1e-4f);
    }
}

// ---------------------------------------------------------------------------
// Patch-operand builder. One uint (2 halves) per thread.
// ---------------------------------------------------------------------------
__global__ __launch_bounds__(256) void k_patch()
{
    int b = blockIdx.y;
    int tid = threadIdx.x;
    if (blockIdx.x < 576) {
        int idx = blockIdx.x * 256 + tid;                 // < 1024*144
        int p  = idx / 144, ku = idx - p * 144;
        int d  = ku >> 4, c2 = ku & 15;
        int dy = d / 3 - 1, dx = d - (d / 3) * 3 - 1;
        int py = p >> 5, px = p & 31;
        int qy = py + dy, qx = px + dx;
        unsigned v = 0;
        if ((unsigned)qy < 32u && (unsigned)qx < 32u)
            v = *(const unsigned*)(g_match16 + ((size_t)b * kHW + qy * 32 + qx) * kC2 + c2 * 2);
        ((unsigned*)g_Ap)[((size_t)b * kHW + p) * 144 + ku] = v;
    } else {
        int idx = (blockIdx.x - 576) * 256 + tid;
        if (idx >= kN * 144) return;
        int n  = idx / 144, ku = idx - n * 144;
        int d  = ku >> 4, c2 = ku & 15;
        int dy = d / 3 - 1, dx = d - (d / 3) * 3 - 1;
        int ny, nx, wl;
        n_geom(n, ny, nx, wl);
        int my = ny + dy, mx = nx + dx;
        unsigned v = 0;
        if ((unsigned)my < (unsigned)wl && (unsigned)mx < (unsigned)wl)
            v = *(const unsigned*)(g_refm16 + ((size_t)b * kN + (n + dy * wl + dx)) * kC2 + c2 * 2);
        ((unsigned*)g_Bp)[((size_t)b * kN + n) * 144 + ku] = v;
    }
}

// ---------------------------------------------------------------------------
// Pipelined patch-GEMM: logit[b][p][n] = invn[n] * sum_{k<288} Ap[p][k]*Bp[n][k]
// 64p x 128n block; A (64x288) resident in smem (cp.async), B double-buffered
// cp.async (9 chunks of BK=32). 8 warps = 2(p) x 4(n), warp 32x32.
// Epilogue staged in smem (reuses A region) -> coalesced fp32 stores.
// ---------------------------------------------------------------------------
__global__ __launch_bounds__(256) void k_gemm1p()
{
    constexpr int SAA = 296;     // A smem stride (halves): 592B -> conflict-free
    constexpr int SAB = 40;      // B smem stride (halves): 80B  -> conflict-free
    extern __shared__ char dyn[];
    __half* As = (__half*)dyn;                       // [64][296]
    __half* Bs = (__half*)(dyn + 64 * SAA * 2);      // [2][128][40]
    float*  Ss = (float*)dyn;                        // reused: [64][132]
    __shared__ float inv_s[128];

    int b  = blockIdx.z;
    int p0 = blockIdx.y * 64;
    int n0 = blockIdx.x * 128;
    const __half* Ab = g_Ap + (size_t)b * kHW * kKP;
    const __half* Bb = g_Bp + (size_t)b * kN  * kKP;
    int tid  = threadIdx.x;
    int lane = tid & 31, warp = tid >> 5;
    int wm = (warp & 1) * 32;
    int wn = (warp >> 1) * 32;
    int gid = lane >> 2, tig = lane & 3;

    if (tid < 128) {
        int n = n0 + tid;
        inv_s[tid] = (n < kN) ? g_invn[(size_t)b * kN + n] : 0.f;
    }

    unsigned aBase = (unsigned)__cvta_generic_to_shared(As);
    unsigned bBase = (unsigned)__cvta_generic_to_shared(Bs);

    // A: 64 rows x 288 halves = 2304 16B granules (9 per thread)
#pragma unroll
    for (int j = 0; j < 9; j++) {
        int i = tid + j * 256;
        int row = i / 36, g = i - row * 36;
        CP_ASYNC16(aBase + row * (SAA * 2) + g * 16,
                   Ab + (size_t)(p0 + row) * kKP + g * 8);
    }
    auto loadB = [&](int kc, int buf) {
#pragma unroll
        for (int j = 0; j < 2; j++) {
            int i = tid + j * 256;
            int row = i >> 2, g = i & 3;
            CP_ASYNC16(bBase + buf * (128 * SAB * 2) + row * (SAB * 2) + g * 16,
                       Bb + (size_t)(n0 + row) * kKP + kc * 32 + g * 8);
        }
    };
    loadB(0, 0); CP_COMMIT();   // g0: A + B0
    loadB(1, 1); CP_COMMIT();   // g1: B1

    float acc[2][4][4] = {};
    for (int kc = 0; kc < 9; kc++) {
        CP_WAIT1();             // group kc drained
        __syncthreads();
        const __half* Bbuf = Bs + (kc & 1) * (128 * SAB);
#pragma unroll
        for (int ks = 0; ks < 2; ks++) {
            int kb = kc * 32 + ks * 16;
            unsigned a[2][4], bf[4][2];
#pragma unroll
            for (int mt = 0; mt < 2; mt++) {
                const __half* ap = &As[(wm + mt * 16 + gid) * SAA + kb + tig * 2];
                a[mt][0] = *(const unsigned*)(ap);
                a[mt][1] = *(const unsigned*)(ap + 8 * SAA);
                a[mt][2] = *(const unsigned*)(ap + 8);
                a[mt][3] = *(const unsigned*)(ap + 8 * SAA + 8);
            }
#pragma unroll
            for (int nt = 0; nt < 4; nt++) {
                const __half* bp = &Bbuf[(wn + nt * 8 + gid) * SAB + ks * 16 + tig * 2];
                bf[nt][0] = *(const unsigned*)(bp);
                bf[nt][1] = *(const unsigned*)(bp + 8);
            }
#pragma unroll
            for (int mt = 0; mt < 2; mt++)
#pragma unroll
                for (int nt = 0; nt < 4; nt++) {
                    asm volatile(
                        "mma.sync.aligned.m16n8k16.row.col.f32.f16.f16.f32 "
                        "{%0,%1,%2,%3}, {%4,%5,%6,%7}, {%8,%9}, {%0,%1,%2,%3};"
                        : "+f"(acc[mt][nt][0]), "+f"(acc[mt][nt][1]),
                          "+f"(acc[mt][nt][2]), "+f"(acc[mt][nt][3])
                        : "r"(a[mt][0]), "r"(a[mt][1]), "r"(a[mt][2]), "r"(a[mt][3]),
                          "r"(bf[nt][0]), "r"(bf[nt][1]));
                }
        }
        __syncthreads();        // all warps done with buf (kc&1) before refill
        if (kc + 2 < 9) loadB(kc + 2, kc & 1);
        CP_COMMIT();            // unconditional: keeps group numbering aligned
    }
    __syncthreads();

    // stage fp32 tile (reuses A region) then coalesced masked stores w/ invn
#pragma unroll
    for (int mt = 0; mt < 2; mt++) {
        int r = wm + mt * 16 + gid;
#pragma unroll
        for (int nt = 0; nt < 4; nt++) {
            int cc = wn + nt * 8 + tig * 2;
            Ss[r * 132 + cc]           = acc[mt][nt][0];
            Ss[r * 132 + cc + 1]       = acc[mt][nt][1];
            Ss[(r + 8) * 132 + cc]     = acc[mt][nt][2];
            Ss[(r + 8) * 132 + cc + 1] = acc[mt][nt][3];
        }
    }
    __syncthreads();
    float* Lb = g_logit + (size_t)b * kHW * kNS;
#pragma unroll
    for (int idx = tid; idx < 64 * 128; idx += 256) {
        int row = idx >> 7, col = idx & 127;
        int n = n0 + col;
        if (n < kN)
            Lb[(size_t)(p0 + row) * kNS + n] = Ss[row * 132 + col] * inv_s[col];
    }
}

// ---------------------------------------------------------------------------
// Stencil-free softmax with ex2.approx.f16x2 (logits pre-scaled by log2e).
// ---------------------------------------------------------------------------
__global__ __launch_bounds__(256) void k_softmax()
{
    __shared__ float row[kNS];
    __shared__ unsigned short nps[kNS];
    __shared__ float red[8];
    int p = blockIdx.x, b = blockIdx.y;
    int tid = threadIdx.x;
    int lane = tid & 31, wid = tid >> 5;
    const float* L = g_logit + ((size_t)b * kHW + p) * kNS;

    float mx = -3.4e38f;
    for (int n = tid; n < kN; n += 256) {
        float v = L[n];
        row[n] = v;
        nps[n] = (unsigned short)(g_mapn[n] & 0xFFFFu);
        mx = fmaxf(mx, v);
    }
#pragma unroll
    for (int o = 16; o; o >>= 1) mx = fmaxf(mx, __shfl_xor_sync(0xffffffffu, mx, o));
    if (lane == 0) red[wid] = mx;
    __syncthreads();
    mx = red[0];
#pragma unroll
    for (int i = 1; i < 8; i++) mx = fmaxf(mx, red[i]);
    __syncthreads();

    float sum = 0.f;
    __half* eo = g_e + ((size_t)b * kHW + p) * kNSP;
    for (int n = tid; n < kN; n += 512) {
        int n2 = n + 256;
        bool v2 = n2 < kN;
        float l0 = row[n] - mx;
        float l1 = v2 ? row[n2] - mx : -60.f;
        __half2 h = __floats2half2_rn(l0, l1);
        unsigned hr = *(unsigned*)&h, er;
        asm("ex2.approx.f16x2 %0, %1;" : "=r"(er) : "r"(hr));
        __half2 e2 = *(__half2*)&er;
        float2 ef = __half22float2(e2);
        sum += ef.x;
        eo[nps[n]] = __low2half(e2);
        if (v2) { sum += ef.y; eo[nps[n2]] = __high2half(e2); }
    }
#pragma unroll
    for (int o = 16; o; o >>= 1) sum += __shfl_xor_sync(0xffffffffu, sum, o);
    if (lane == 0) red[wid] = sum;
    __syncthreads();
    if (tid == 0) {
        float s = red[0];
#pragma unroll
        for (int i = 1; i < 8; i++) s += red[i];
        g_inv[(size_t)b * kHW + p] = 1.f / s;
    }
}

// block-uniform p-side validity + q-row indices
__device__ __forceinline__ unsigned p_taps(int p, int* qrow)
{
    int py = p >> 5, px = p & 31;
    unsigned pm = 0;
    int i = 0;
#pragma unroll
    for (int dy = -1; dy <= 1; dy++)
#pragma unroll
        for (int dx = -1; dx <= 1; dx++, i++) {
            int qy = py + dy, qx = px + dx;
            qrow[i] = qy * 32 + qx;
            if ((unsigned)qy < 32u && (unsigned)qx < 32u) pm |= 1u << i;
        }
    return pm;
}

// ---------------------------------------------------------------------------
// T[b][p][n] = sum_d inv[p+d] * e[b][p+d][np+d]  (block per (p,b); hoisted)
// ---------------------------------------------------------------------------
__global__ __launch_bounds__(256) void k_stencilT()
{
    int p = blockIdx.x, b = blockIdx.y;
    int tid = threadIdx.x;

    int qrow[9];
    unsigned pm = p_taps(p, qrow);
    const __half* E = g_e + (size_t)b * kHW * kNSP;
    const __half* Eq[9];
    float iv[9];
#pragma unroll
    for (int i = 0; i < 9; i++) {
        bool v = (pm >> i) & 1u;
        Eq[i] = v ? (E + (size_t)qrow[i] * kNSP) : g_zeroH;
        iv[i] = v ? g_inv[(size_t)b * kHW + qrow[i]] : 0.f;
    }
    __half* To = g_T + ((size_t)b * kHW + p) * kNS;

#pragma unroll 2
    for (int n = tid; n < kN; n += 256) {
        unsigned u = g_mapn[n];
        int np = (int)(u & 0xFFFFu), wss = (int)(u >> 16);
        int cm = np - wss, cp = np + wss;
        float s;
        s = iv[0] * __half2float(Eq[0][cm - 1]);
        s = fmaf(iv[1], __half2float(Eq[1][cm]),     s);
        s = fmaf(iv[2], __half2float(Eq[2][cm + 1]), s);
        s = fmaf(iv[3], __half2float(Eq[3][np - 1]), s);
        s = fmaf(iv[4], __half2float(Eq[4][np]),     s);
        s = fmaf(iv[5], __half2float(Eq[5][np + 1]), s);
        s = fmaf(iv[6], __half2float(Eq[6][cp - 1]), s);
        s = fmaf(iv[7], __half2float(Eq[7][cp]),     s);
        s = fmaf(iv[8], __half2float(Eq[8][cp + 1]), s);
        To[n] = __float2half(s);
    }
}

// ---------------------------------------------------------------------------
// GEMM2 on tensor cores: out[b][c][p] = x[b][c][p] + 0.25*sum_m base*T
// 64c x 128p, BK=64; 8 warps 2(c)x4(p); m16n8k16 HMMA fp32 acc (R7-proven).
// ---------------------------------------------------------------------------
__global__ __launch_bounds__(256) void k_gemm2(
    const float* __restrict__ x, float* __restrict__ out)
{
    constexpr int BK = 64;
    constexpr int SA = 72;
    __shared__ __half As[64 * SA];
    __shared__ __half Bs[128 * SA];
    int b  = blockIdx.y;
    int p0 = blockIdx.x * 128;
    const __half* Ab = g_base16 + (size_t)b * kC * kN;
    const __half* Tb = g_T      + (size_t)b * kHW * kNS;
    int tid  = threadIdx.x;
    int lane = tid & 31, warp = tid >> 5;
    int wc = (warp & 1) * 32;
    int wp = (warp >> 1) * 32;
    int gid = lane >> 2, tig = lane & 3;
    float acc[2][4][4] = {};

    for (int k0 = 0; k0 < kN; k0 += BK) {
#pragma unroll
        for (int j = 0; j < 8; j++) {
            int idx = tid + j * 256;
            int c = idx >> 5, kk = (idx & 31) * 2;
            int k = k0 + kk;
            unsigned v = 0;
            if (k < kN) v = *(const unsigned*)(Ab + (size_t)c * kN + k);
            *(unsigned*)(&As[c * SA + kk]) = v;
        }
#pragma unroll
        for (int j = 0; j < 16; j++) {
            int idx = tid + j * 256;
            int pp = idx >> 5, kk = (idx & 31) * 2;
            int k = k0 + kk;
            unsigned v = 0;
            if (k < kN) v = *(const unsigned*)(Tb + (size_t)(p0 + pp) * kNS + k);
            *(unsigned*)(&Bs[pp * SA + kk]) = v;
        }
        __syncthreads();
#pragma unroll
        for (int ks = 0; ks < 4; ks++) {
            int kb = ks * 16;
            unsigned a[2][4], bf[4][2];
#pragma unroll
            for (int mt = 0; mt < 2; mt++) {
                const __half* ap = &As[(wc + mt * 16 + gid) * SA + kb + tig * 2];
                a[mt][0] = *(const unsigned*)(ap);
                a[mt][1] = *(const unsigned*)(ap + 8 * SA);
                a[mt][2] = *(const unsigned*)(ap + 8);
                a[mt][3] = *(const unsigned*)(ap + 8 * SA + 8);
            }
#pragma unroll
            for (int nt = 0; nt < 4; nt++) {
                const __half* bp = &Bs[(wp + nt * 8 + gid) * SA + kb + tig * 2];
                bf[nt][0] = *(const unsigned*)(bp);
                bf[nt][1] = *(const unsigned*)(bp + 8);
            }
#pragma unroll
            for (int mt = 0; mt < 2; mt++)
#pragma unroll
                for (int nt = 0; nt < 4; nt++) {
                    asm volatile(
                        "mma.sync.aligned.m16n8k16.row.col.f32.f16.f16.f32 "
                        "{%0,%1,%2,%3}, {%4,%5,%6,%7}, {%8,%9}, {%0,%1,%2,%3};"
                        : "+f"(acc[mt][nt][0]), "+f"(acc[mt][nt][1]),
                          "+f"(acc[mt][nt][2]), "+f"(acc[mt][nt][3])
                        : "r"(a[mt][0]), "r"(a[mt][1]), "r"(a[mt][2]), "r"(a[mt][3]),
                          "r"(bf[nt][0]), "r"(bf[nt][1]));
                }
        }
        __syncthreads();
    }

    const float* xb = x   + (size_t)b * kC * kHW;
    float*       ob = out + (size_t)b * kC * kHW;
#pragma unroll
    for (int mt = 0; mt < 2; mt++) {
        int c = wc + mt * 16 + gid;
#pragma unroll
        for (int nt = 0; nt < 4; nt++) {
            int pc = p0 + wp + nt * 8 + tig * 2;
            ob[(size_t)c * kHW + pc]           = fmaf(0.25f, acc[mt][nt][0], xb[(size_t)c * kHW + pc]);
            ob[(size_t)c * kHW + pc + 1]       = fmaf(0.25f, acc[mt][nt][1], xb[(size_t)c * kHW + pc + 1]);
            ob[(size_t)(c + 8) * kHW + pc]     = fmaf(0.25f, acc[mt][nt][2], xb[(size_t)(c + 8) * kHW + pc]);
            ob[(size_t)(c + 8) * kHW + pc + 1] = fmaf(0.25f, acc[mt][nt][3], xb[(size_t)(c + 8) * kHW + pc + 1]);
        }
    }
}

// ---------------------------------------------------------------------------
extern "C" void kernel_launch(void* const* d_in, const int* in_sizes, int n_in,
                              void* d_out, int out_size)
{
    (void)in_sizes; (void)n_in; (void)out_size;
    const float* x       = (const float*)d_in[0];
    const float* w_base  = (const float*)d_in[1];
    const float* b_base  = (const float*)d_in[2];
    const float* a_base  = (const float*)d_in[3];
    const float* w_match = (const float*)d_in[4];
    const float* b_match = (const float*)d_in[5];
    const float* a_match = (const float*)d_in[6];
    const float* w_asm   = (const float*)d_in[7];
    const float* b_asm   = (const float*)d_in[8];
    const float* a_asm   = (const float*)d_in[9];
    float* out = (float*)d_out;

    static bool attr_done = false;
    if (!attr_done) {
        cudaFuncSetAttribute(k_gemm1p, cudaFuncAttributeMaxDynamicSharedMemorySize, kG1Smem);
        attr_done = true;
    }

    {
        dim3 g(13, kB);
        k_conv_pyr<<<g, 256>>>(x, w_match, b_match, a_match, w_asm, b_asm, a_asm); // 1
    }
    {
        dim3 g(4, kB);
        k_conv_main<<<g, 256>>>(x, w_base, b_base, a_base);                        // 2 (+invn tail)
    }
    {
        dim3 g(576 + 1844, kB);
        k_patch<<<g, 256>>>();                                                     // 3
    }
    {
        dim3 g((kN + 127) / 128, kHW / 64, kB);
        k_gemm1p<<<g, 256, kG1Smem>>>();                                           // 4 (profiled)
    }
    {
        dim3 g(kHW, kB);
        k_softmax<<<g, 256>>>();                                                   // 5
        k_stencilT<<<g, 256>>>();                                                  // 6
    }
    {
        dim3 g(kHW / 128, kB);
        k_gemm2<<<g, 256>>>(x, out);                                               // 7
    }
}

// round 17
// speedup vs baseline: 1.1645x; 1.1028x over previous
#include <cuda_runtime.h>
#include <cuda_fp16.h>

// ---------------------------------------------------------------------------
// PyramidAttention (UrbanODE core), B=32, C=64, H=W=32, 5 scales, N=3278.
//
//   S[m,q]      = sum_c refm[c,m] * match[c,q]              (fp16 HMMA, fp16 S)
//   logit[n,p]  = 10*invnorm[n] * sum_d S[n+d, p+d]
//   e           = exp(logit - max), inv[p] = 1/sum e        (fp16 e + fp32 inv)
//   T[p,m]      = sum_d inv[p+d] * e[p+d][m+d]
//   out[c,p]    = x[c,p] + 0.25 * sum_m base[c,m] * T[p,m]  (fp16 HMMA)
//
// R17: revert to R14 (best measured, 1081us) — the patch-GEMM branch lost
// twice. New: DUAL-P softmax — two p-rows per block share the per-n decode
// (mapn, invn, column bases), which dominated the 433us issue-bound kernel.
// Invalid p-taps read a global zero tail row (branch-free int offsets).
// ---------------------------------------------------------------------------

namespace {
constexpr int kB   = 32;
constexpr int kC   = 64;
constexpr int kC2  = 32;
constexpr int kHW  = 1024;
constexpr int kN   = 3278;   // 1024+784+625+484+361
constexpr int kNS  = 3280;   // valid-layout row stride (T)
constexpr int kNSP = 3808;   // padded-layout row stride (S, e, sq)
constexpr int kG1Smem = 128 * 132 * 2;   // gemm1 dynamic smem (fp16 tile)
}

// scratch (device globals zero-initialized; guard cells / zero rows never written)
__device__ __half   g_match16[(size_t)kB * kHW * kC2]; // [p][c] fp16 (A row-major)
__device__ __half   g_refm16 [(size_t)kB * kN  * kC2]; // [n][c] fp16 (B col-major)
__device__ __half   g_base16 [(size_t)kB * kC  * kN];  // [c][n] fp16
__device__ float    g_sqp    [(size_t)kB * kNSP];
__device__ float    g_invn   [(size_t)kB * kN];
__device__ float    g_inv    [(size_t)kB * kHW];
__device__ unsigned g_mapn   [kN];                     // np | (ws<<16)
__device__ __half   g_zeroH  [kNSP + 64];              // never written
__device__ __half   g_S      [(size_t)kB * kHW * kNSP + 2 * kNSP]; // + zero tail
__device__ __half   g_e      [(size_t)kB * kHW * kNSP];
__device__ __half   g_T      [(size_t)kB * kHW * kNS];

// pyramid pixel -> (level-local y, x, level width)
__device__ __forceinline__ void n_geom(int n, int& ny, int& nx, int& wl)
{
    if (n < 1024)      { int loc = n;        ny = loc >> 5;  nx = loc & 31;     wl = 32; }
    else if (n < 1808) { int loc = n - 1024; ny = loc / 28;  nx = loc - ny*28;  wl = 28; }
    else if (n < 2433) { int loc = n - 1808; ny = loc / 25;  nx = loc - ny*25;  wl = 25; }
    else if (n < 2917) { int loc = n - 2433; ny = loc / 22;  nx = loc - ny*22;  wl = 22; }
    else               { int loc = n - 2917; ny = loc / 19;  nx = loc - ny*19;  wl = 19; }
}

// valid n -> padded index np and padded width ws
__device__ __forceinline__ void n_pad(int n, int& np, int& ws)
{
    int ny, nx, wl;
    n_geom(n, ny, nx, wl);
    int pb;
    if (n < 1024)      pb = 0;
    else if (n < 1808) pb = 1156;
    else if (n < 2433) pb = 2056;
    else if (n < 2917) pb = 2785;
    else               pb = 3361;
    ws = wl + 2;
    np = pb + (ny + 1) * ws + (nx + 1);
}

// ---------------------------------------------------------------------------
// Pyramid projections: refm16 [n][c] + sq + base16 [c][n] + mapn.
// ---------------------------------------------------------------------------
__global__ __launch_bounds__(256) void k_conv_pyr(
    const float* __restrict__ x,
    const float* __restrict__ w_match, const float* __restrict__ b_match,
    const float* __restrict__ a_match,
    const float* __restrict__ w_asm,   const float* __restrict__ b_asm,
    const float* __restrict__ a_asm)
{
    __shared__ float ws[kC2 * kC + kC * kC];
    int b = blockIdx.y;
    int tid = threadIdx.x;
    for (int i = tid; i < kC2 * kC; i += 256) ws[i] = w_match[i];
    for (int i = tid; i < kC * kC; i += 256)  ws[kC2 * kC + i] = w_asm[i];
    __syncthreads();
    int n = blockIdx.x * 256 + tid;
    if (n >= kN) return;

    int ny, nx, wl;
    n_geom(n, ny, nx, wl);
    int sy = (ny * 32) / wl;
    int sx = (nx * 32) / wl;
    const float* xb = x + ((size_t)b * kC) * kHW + sy * 32 + sx;

    float accM[kC2], accA[kC];
#pragma unroll
    for (int co = 0; co < kC2; co++) accM[co] = b_match[co];
#pragma unroll
    for (int co = 0; co < kC; co++)  accA[co] = b_asm[co];
#pragma unroll 2
    for (int c = 0; c < kC; c++) {
        float xv = xb[(size_t)c * kHW];
#pragma unroll
        for (int co = 0; co < kC2; co++) accM[co] = fmaf(ws[co * kC + c], xv, accM[co]);
#pragma unroll
        for (int co = 0; co < kC; co++)  accA[co] = fmaf(ws[kC2 * kC + co * kC + c], xv, accA[co]);
    }
    float alM = a_match[0], alA = a_asm[0];
    __half* obM = g_refm16 + ((size_t)b * kN + n) * kC2;
    float sq = 0.f;
#pragma unroll
    for (int co = 0; co < kC2; co++) {
        float v = accM[co];
        v = v >= 0.f ? v : alM * v;
        obM[co] = __float2half(v);
        sq = fmaf(v, v, sq);
    }
    __half* obA = g_base16 + (size_t)b * kC * kN + n;
#pragma unroll
    for (int co = 0; co < kC; co++) {
        float v = accA[co];
        v = v >= 0.f ? v : alA * v;
        obA[(size_t)co * kN] = __float2half(v);
    }
    int np, wss;
    n_pad(n, np, wss);
    g_sqp[(size_t)b * kNSP + np] = sq;
    if (b == 0) g_mapn[n] = (unsigned)np | ((unsigned)wss << 16);
}

// ---------------------------------------------------------------------------
// Main projection: match16 [p][c] fp16. Tail: invnorm.
// ---------------------------------------------------------------------------
__global__ __launch_bounds__(256) void k_conv_main(
    const float* __restrict__ x, const float* __restrict__ w,
    const float* __restrict__ bias, const float* __restrict__ a)
{
    __shared__ float ws[kC2 * kC];
    int b = blockIdx.y;
    int tid = threadIdx.x;
    for (int i = tid; i < kC2 * kC; i += 256) ws[i] = w[i];
    __syncthreads();
    int p = blockIdx.x * 256 + tid;
    const float* xb = x + ((size_t)b * kC) * kHW + p;
    float acc[kC2];
#pragma unroll
    for (int co = 0; co < kC2; co++) acc[co] = bias[co];
#pragma unroll 2
    for (int c = 0; c < kC; c++) {
        float xv = xb[(size_t)c * kHW];
#pragma unroll
        for (int co = 0; co < kC2; co++) acc[co] = fmaf(ws[co * kC + c], xv, acc[co]);
    }
    float al = a[0];
    __half* ob = g_match16 + ((size_t)b * kHW + p) * kC2;
#pragma unroll
    for (int co = 0; co < kC2; co++) {
        float v = acc[co];
        ob[co] = __float2half(v >= 0.f ? v : al * v);
    }

    // ---- invnorm tail: grid-stride over all (b,n) ----
    int nthreads = gridDim.x * gridDim.y * 256;
    int gid0 = (b * gridDim.x + blockIdx.x) * 256 + tid;
    for (int t = gid0; t < kB * kN; t += nthreads) {
        int n = t % kN, bb = t / kN;
        unsigned u = g_mapn[n];
        int np = (int)(u & 0xFFFFu), wss = (int)(u >> 16);
        const float* sp = g_sqp + (size_t)bb * kNSP;
        int cm = np - wss, cp = np + wss;
        float s = sp[cm-1] + sp[cm] + sp[cm+1]
                + sp[np-1] + sp[np] + sp[np+1]
                + sp[cp-1] + sp[cp] + sp[cp+1];
        g_invn[t] = 10.f / fmaxf(sqrtf(s), 1e-4f);
    }
}

// ---------------------------------------------------------------------------
// GEMM1 on tensor cores, smem-staged fp16 epilogue (R13/R14-measured).
// 128p x 128n block, K=32 (2 ksteps). 8 warps = 4(p) x 2(n), warp 32x64.
// ---------------------------------------------------------------------------
__global__ __launch_bounds__(256) void k_gemm1()
{
    constexpr int SA = 40;                  // half stride (32 + 8 pad)
    extern __shared__ char dyn[];
    __half* As = (__half*)dyn;              // [128][SA]
    __half* Bs = As + 128 * SA;             // [128][SA]
    __half* Ss = (__half*)dyn;              // reused after MMA: [128][132] fp16
    __shared__ int nps[128];
    int b  = blockIdx.z;
    int p0 = blockIdx.y * 128;
    int n0 = blockIdx.x * 128;
    const __half* Ab = g_match16 + (size_t)b * kHW * kC2;
    const __half* Bb = g_refm16  + (size_t)b * kN  * kC2;
    int tid  = threadIdx.x;
    int lane = tid & 31, warp = tid >> 5;
    int wm = (warp & 3) * 32;
    int wn = (warp >> 2) * 64;
    int gid = lane >> 2, tig = lane & 3;

    // stage A, B, mapn
#pragma unroll
    for (int j = 0; j < 8; j++) {
        int idx = tid + j * 256;
        int row = idx >> 4, kk = (idx & 15) * 2;
        *(unsigned*)(&As[row * SA + kk]) =
            *(const unsigned*)(Ab + (size_t)(p0 + row) * kC2 + kk);
        int n = n0 + row;
        unsigned v = 0;
        if (n < kN) v = *(const unsigned*)(Bb + (size_t)n * kC2 + kk);
        *(unsigned*)(&Bs[row * SA + kk]) = v;
    }
    if (tid < 128) {
        int n = n0 + tid;
        nps[tid] = (n < kN) ? (int)(g_mapn[n] & 0xFFFFu) : -1;
    }
    __syncthreads();

    float acc[2][8][4] = {};
#pragma unroll
    for (int ks = 0; ks < 2; ks++) {
        int kb = ks * 16;
        unsigned a[2][4], bf[8][2];
#pragma unroll
        for (int mt = 0; mt < 2; mt++) {
            const __half* ap = &As[(wm + mt * 16 + gid) * SA + kb + tig * 2];
            a[mt][0] = *(const unsigned*)(ap);
            a[mt][1] = *(const unsigned*)(ap + 8 * SA);
            a[mt][2] = *(const unsigned*)(ap + 8);
            a[mt][3] = *(const unsigned*)(ap + 8 * SA + 8);
        }
#pragma unroll
        for (int nt = 0; nt < 8; nt++) {
            const __half* bp = &Bs[(wn + nt * 8 + gid) * SA + kb + tig * 2];
            bf[nt][0] = *(const unsigned*)(bp);
            bf[nt][1] = *(const unsigned*)(bp + 8);
        }
#pragma unroll
        for (int mt = 0; mt < 2; mt++)
#pragma unroll
            for (int nt = 0; nt < 8; nt++) {
                asm volatile(
                    "mma.sync.aligned.m16n8k16.row.col.f32.f16.f16.f32 "
                    "{%0,%1,%2,%3}, {%4,%5,%6,%7}, {%8,%9}, {%0,%1,%2,%3};"
                    : "+f"(acc[mt][nt][0]), "+f"(acc[mt][nt][1]),
                      "+f"(acc[mt][nt][2]), "+f"(acc[mt][nt][3])
                    : "r"(a[mt][0]), "r"(a[mt][1]), "r"(a[mt][2]), "r"(a[mt][3]),
                      "r"(bf[nt][0]), "r"(bf[nt][1]));
            }
    }
    __syncthreads();   // done reading As/Bs; smem reused as fp16 tile

    // stage accumulators into the fp16 tile (half2-packed)
#pragma unroll
    for (int mt = 0; mt < 2; mt++) {
        int r = wm + mt * 16 + gid;
#pragma unroll
        for (int nt = 0; nt < 8; nt++) {
            int cc = wn + nt * 8 + tig * 2;
            *(__half2*)(&Ss[r * 132 + cc]) =
                __floats2half2_rn(acc[mt][nt][0], acc[mt][nt][1]);
            *(__half2*)(&Ss[(r + 8) * 132 + cc]) =
                __floats2half2_rn(acc[mt][nt][2], acc[mt][nt][3]);
        }
    }
    __syncthreads();

    // coalesced write-out (lane-contiguous n; np contiguous within a level)
    __half* Sb = g_S + (size_t)b * kHW * kNSP;
#pragma unroll
    for (int idx = tid; idx < 128 * 128; idx += 256) {
        int row = idx >> 7, col = idx & 127;
        int np = nps[col];
        if (np >= 0) Sb[(size_t)(p0 + row) * kNSP + np] = Ss[row * 132 + col];
    }
}

// block-uniform p-side validity + q-row indices
__device__ __forceinline__ unsigned p_taps(int p, int* qrow)
{
    int py = p >> 5, px = p & 31;
    unsigned pm = 0;
    int i = 0;
#pragma unroll
    for (int dy = -1; dy <= 1; dy++)
#pragma unroll
        for (int dx = -1; dx <= 1; dx++, i++) {
            int qy = py + dy, qx = px + dx;
            qrow[i] = qy * 32 + qx;
            if ((unsigned)qy < 32u && (unsigned)qx < 32u) pm |= 1u << i;
        }
    return pm;
}

// ---------------------------------------------------------------------------
// DUAL-P fused softmax: block handles p and p+512; per-n decode (mapn, invn,
// column bases) shared across both rows. Invalid p-taps read the zero tail
// row of g_S via int offsets (branch-free).
// ---------------------------------------------------------------------------
__global__ __launch_bounds__(256) void k_softmax()
{
    __shared__ float row0[kNS], row1[kNS];
    __shared__ unsigned short nps[kNS];
    __shared__ float red0[8], red1[8];
    int pA = blockIdx.x, pBp = blockIdx.x + 512, b = blockIdx.y;
    int tid = threadIdx.x;
    int lane = tid & 31, wid = tid >> 5;

    const __half* S = g_S + (size_t)b * kHW * kNSP;
    int zoff = (kB - b) * kHW * kNSP;    // global zero tail row, relative to S
    int qr0[9], qr1[9];
    unsigned pm0 = p_taps(pA, qr0), pm1 = p_taps(pBp, qr1);
    int qo0[9], qo1[9];
#pragma unroll
    for (int i = 0; i < 9; i++) {
        qo0[i] = ((pm0 >> i) & 1u) ? qr0[i] * kNSP : zoff;
        qo1[i] = ((pm1 >> i) & 1u) ? qr1[i] * kNSP : zoff;
    }
    const float* invn = g_invn + (size_t)b * kN;

    float mx0 = -3.4e38f, mx1 = -3.4e38f;
    for (int n = tid; n < kN; n += 256) {
        unsigned u = g_mapn[n];
        int np = (int)(u & 0xFFFFu), wss = (int)(u >> 16);
        nps[n] = (unsigned short)np;
        int cm = np - wss, cp = np + wss;
        float iv = invn[n];
        float s0 = __half2float(S[qo0[0] + cm - 1]) + __half2float(S[qo0[1] + cm])
                 + __half2float(S[qo0[2] + cm + 1]) + __half2float(S[qo0[3] + np - 1])
                 + __half2float(S[qo0[4] + np])     + __half2float(S[qo0[5] + np + 1])
                 + __half2float(S[qo0[6] + cp - 1]) + __half2float(S[qo0[7] + cp])
                 + __half2float(S[qo0[8] + cp + 1]);
        float s1 = __half2float(S[qo1[0] + cm - 1]) + __half2float(S[qo1[1] + cm])
                 + __half2float(S[qo1[2] + cm + 1]) + __half2float(S[qo1[3] + np - 1])
                 + __half2float(S[qo1[4] + np])     + __half2float(S[qo1[5] + np + 1])
                 + __half2float(S[qo1[6] + cp - 1]) + __half2float(S[qo1[7] + cp])
                 + __half2float(S[qo1[8] + cp + 1]);
        s0 *= iv; s1 *= iv;
        row0[n] = s0; row1[n] = s1;
        mx0 = fmaxf(mx0, s0); mx1 = fmaxf(mx1, s1);
    }
#pragma unroll
    for (int o = 16; o; o >>= 1) {
        mx0 = fmaxf(mx0, __shfl_xor_sync(0xffffffffu, mx0, o));
        mx1 = fmaxf(mx1, __shfl_xor_sync(0xffffffffu, mx1, o));
    }
    if (lane == 0) { red0[wid] = mx0; red1[wid] = mx1; }
    __syncthreads();
    mx0 = red0[0]; mx1 = red1[0];
#pragma unroll
    for (int i = 1; i < 8; i++) {
        mx0 = fmaxf(mx0, red0[i]);
        mx1 = fmaxf(mx1, red1[i]);
    }
    __syncthreads();

    float sum0 = 0.f, sum1 = 0.f;
    __half* eo0 = g_e + ((size_t)b * kHW + pA)  * kNSP;
    __half* eo1 = g_e + ((size_t)b * kHW + pBp) * kNSP;
    for (int n = tid; n < kN; n += 256) {
        float e0 = __expf(row0[n] - mx0);
        float e1 = __expf(row1[n] - mx1);
        sum0 += e0; sum1 += e1;
        int np = nps[n];
        eo0[np] = __float2half(e0);
        eo1[np] = __float2half(e1);
    }
#pragma unroll
    for (int o = 16; o; o >>= 1) {
        sum0 += __shfl_xor_sync(0xffffffffu, sum0, o);
        sum1 += __shfl_xor_sync(0xffffffffu, sum1, o);
    }
    if (lane == 0) { red0[wid] = sum0; red1[wid] = sum1; }
    __syncthreads();
    if (tid == 0) {
        float s0 = red0[0], s1 = red1[0];
#pragma unroll
        for (int i = 1; i < 8; i++) { s0 += red0[i]; s1 += red1[i]; }
        g_inv[(size_t)b * kHW + pA]  = 1.f / s0;
        g_inv[(size_t)b * kHW + pBp] = 1.f / s1;
    }
}

// ---------------------------------------------------------------------------
// T[b][p][n] = sum_d inv[p+d] * e[b][p+d][np+d]  (block per (p,b); hoisted)
// ---------------------------------------------------------------------------
__global__ __launch_bounds__(256) void k_stencilT()
{
    int p = blockIdx.x, b = blockIdx.y;
    int tid = threadIdx.x;

    int qrow[9];
    unsigned pm = p_taps(p, qrow);
    const __half* E = g_e + (size_t)b * kHW * kNSP;
    const __half* Eq[9];
    float iv[9];
#pragma unroll
    for (int i = 0; i < 9; i++) {
        bool v = (pm >> i) & 1u;
        Eq[i] = v ? (E + (size_t)qrow[i] * kNSP) : g_zeroH;
        iv[i] = v ? g_inv[(size_t)b * kHW + qrow[i]] : 0.f;
    }
    __half* To = g_T + ((size_t)b * kHW + p) * kNS;

#pragma unroll 2
    for (int n = tid; n < kN; n += 256) {
        unsigned u = g_mapn[n];
        int np = (int)(u & 0xFFFFu), wss = (int)(u >> 16);
        int cm = np - wss, cp = np + wss;
        float s;
        s = iv[0] * __half2float(Eq[0][cm - 1]);
        s = fmaf(iv[1], __half2float(Eq[1][cm]),     s);
        s = fmaf(iv[2], __half2float(Eq[2][cm + 1]), s);
        s = fmaf(iv[3], __half2float(Eq[3][np - 1]), s);
        s = fmaf(iv[4], __half2float(Eq[4][np]),     s);
        s = fmaf(iv[5], __half2float(Eq[5][np + 1]), s);
        s = fmaf(iv[6], __half2float(Eq[6][cp - 1]), s);
        s = fmaf(iv[7], __half2float(Eq[7][cp]),     s);
        s = fmaf(iv[8], __half2float(Eq[8][cp + 1]), s);
        To[n] = __float2half(s);
    }
}

// ---------------------------------------------------------------------------
// GEMM2 on tensor cores: out[b][c][p] = x[b][c][p] + 0.25*sum_m base*T
// 64c x 128p, BK=64; 8 warps 2(c)x4(p); m16n8k16 HMMA fp32 acc (R7-proven).
// ---------------------------------------------------------------------------
__global__ __launch_bounds__(256) void k_gemm2(
    const float* __restrict__ x, float* __restrict__ out)
{
    constexpr int BK = 64;
    constexpr int SA = 72;
    __shared__ __half As[64 * SA];
    __shared__ __half Bs[128 * SA];
    int b  = blockIdx.y;
    int p0 = blockIdx.x * 128;
    const __half* Ab = g_base16 + (size_t)b * kC * kN;
    const __half* Tb = g_T      + (size_t)b * kHW * kNS;
    int tid  = threadIdx.x;
    int lane = tid & 31, warp = tid >> 5;
    int wc = (warp & 1) * 32;
    int wp = (warp >> 1) * 32;
    int gid = lane >> 2, tig = lane & 3;
    float acc[2][4][4] = {};

    for (int k0 = 0; k0 < kN; k0 += BK) {
#pragma unroll
        for (int j = 0; j < 8; j++) {
            int idx = tid + j * 256;
            int c = idx >> 5, kk = (idx & 31) * 2;
            int k = k0 + kk;
            unsigned v = 0;
            if (k < kN) v = *(const unsigned*)(Ab + (size_t)c * kN + k);
            *(unsigned*)(&As[c * SA + kk]) = v;
        }
#pragma unroll
        for (int j = 0; j < 16; j++) {
            int idx = tid + j * 256;
            int pp = idx >> 5, kk = (idx & 31) * 2;
            int k = k0 + kk;
            unsigned v = 0;
            if (k < kN) v = *(const unsigned*)(Tb + (size_t)(p0 + pp) * kNS + k);
            *(unsigned*)(&Bs[pp * SA + kk]) = v;
        }
        __syncthreads();
#pragma unroll
        for (int ks = 0; ks < 4; ks++) {
            int kb = ks * 16;
            unsigned a[2][4], bf[4][2];
#pragma unroll
            for (int mt = 0; mt < 2; mt++) {
                const __half* ap = &As[(wc + mt * 16 + gid) * SA + kb + tig * 2];
                a[mt][0] = *(const unsigned*)(ap);
                a[mt][1] = *(const unsigned*)(ap + 8 * SA);
                a[mt][2] = *(const unsigned*)(ap + 8);
                a[mt][3] = *(const unsigned*)(ap + 8 * SA + 8);
            }
#pragma unroll
            for (int nt = 0; nt < 4; nt++) {
                const __half* bp = &Bs[(wp + nt * 8 + gid) * SA + kb + tig * 2];
                bf[nt][0] = *(const unsigned*)(bp);
                bf[nt][1] = *(const unsigned*)(bp + 8);
            }
#pragma unroll
            for (int mt = 0; mt < 2; mt++)
#pragma unroll
                for (int nt = 0; nt < 4; nt++) {
                    asm volatile(
                        "mma.sync.aligned.m16n8k16.row.col.f32.f16.f16.f32 "
                        "{%0,%1,%2,%3}, {%4,%5,%6,%7}, {%8,%9}, {%0,%1,%2,%3};"
                        : "+f"(acc[mt][nt][0]), "+f"(acc[mt][nt][1]),
                          "+f"(acc[mt][nt][2]), "+f"(acc[mt][nt][3])
                        : "r"(a[mt][0]), "r"(a[mt][1]), "r"(a[mt][2]), "r"(a[mt][3]),
                          "r"(bf[nt][0]), "r"(bf[nt][1]));
                }
        }
        __syncthreads();
    }

    const float* xb = x   + (size_t)b * kC * kHW;
    float*       ob = out + (size_t)b * kC * kHW;
#pragma unroll
    for (int mt = 0; mt < 2; mt++) {
        int c = wc + mt * 16 + gid;
#pragma unroll
        for (int nt = 0; nt < 4; nt++) {
            int pc = p0 + wp + nt * 8 + tig * 2;
            ob[(size_t)c * kHW + pc]           = fmaf(0.25f, acc[mt][nt][0], xb[(size_t)c * kHW + pc]);
            ob[(size_t)c * kHW + pc + 1]       = fmaf(0.25f, acc[mt][nt][1], xb[(size_t)c * kHW + pc + 1]);
            ob[(size_t)(c + 8) * kHW + pc]     = fmaf(0.25f, acc[mt][nt][2], xb[(size_t)(c + 8) * kHW + pc]);
            ob[(size_t)(c + 8) * kHW + pc + 1] = fmaf(0.25f, acc[mt][nt][3], xb[(size_t)(c + 8) * kHW + pc + 1]);
        }
    }
}

// ---------------------------------------------------------------------------
extern "C" void kernel_launch(void* const* d_in, const int* in_sizes, int n_in,
                              void* d_out, int out_size)
{
    (void)in_sizes; (void)n_in; (void)out_size;
    const float* x       = (const float*)d_in[0];
    const float* w_base  = (const float*)d_in[1];
    const float* b_base  = (const float*)d_in[2];
    const float* a_base  = (const float*)d_in[3];
    const float* w_match = (const float*)d_in[4];
    const float* b_match = (const float*)d_in[5];
    const float* a_match = (const float*)d_in[6];
    const float* w_asm   = (const float*)d_in[7];
    const float* b_asm   = (const float*)d_in[8];
    const float* a_asm   = (const float*)d_in[9];
    float* out = (float*)d_out;

    static bool attr_done = false;
    if (!attr_done) {
        cudaFuncSetAttribute(k_gemm1, cudaFuncAttributeMaxDynamicSharedMemorySize, kG1Smem);
        attr_done = true;
    }

    {
        dim3 g(13, kB);
        k_conv_pyr<<<g, 256>>>(x, w_match, b_match, a_match, w_asm, b_asm, a_asm); // 1
    }
    {
        dim3 g(4, kB);
        k_conv_main<<<g, 256>>>(x, w_base, b_base, a_base);                        // 2 (+invn tail)
    }
    {
        dim3 g((kN + 127) / 128, kHW / 128, kB);
        k_gemm1<<<g, 256, kG1Smem>>>();                                            // 3
    }
    {
        dim3 g(512, kB);
        k_softmax<<<g, 256>>>();                                                   // 4 (profiled, dual-p)
    }
    {
        dim3 g(kHW, kB);
        k_stencilT<<<g, 256>>>();                                                  // 5
    }
    {
        dim3 g(kHW / 128, kB);
        k_gemm2<<<g, 256>>>(x, out);                                               // 6
    }
}